// round 2
// baseline (speedup 1.0000x reference)
#include <cuda_runtime.h>
#include <math.h>

#define B 4
#define L 2048
#define H 8
#define D 64
#define S 40
#define U 40
#define HD (H*D)
#define CHUNK 128
#define NCHUNK (L/CHUNK)
#define SCALE 0.125f   /* 1/sqrt(64) */

// scratch (allocation-free rule: __device__ globals)
__device__ float g_M[B*H*L];
__device__ int   g_top[B*H*U];
__device__ float g_csum[B*H*NCHUNK*D];

// ---------------------------------------------------------------------------
// Kernel 1: M[b,h,q] = max_s dot(Q[b,h,q], K[b,h,idx[q,s]]) - sum_s/L
// one warp per (b,h,q); float2 per lane over D=64
// ---------------------------------------------------------------------------
__global__ void compute_M_kernel(const float* __restrict__ Q,
                                 const float* __restrict__ K,
                                 const int*   __restrict__ idx) {
    int gw   = (blockIdx.x * blockDim.x + threadIdx.x) >> 5;
    int lane = threadIdx.x & 31;
    if (gw >= B*H*L) return;
    int q = gw % L;
    int h = (gw / L) % H;
    int b = gw / (L*H);

    const float2* qp = (const float2*)(Q + (((size_t)b*L + q)*H + h)*D);
    float2 qv = qp[lane];

    float mx = -INFINITY, sm = 0.f;
    #pragma unroll 4
    for (int s = 0; s < S; s++) {
        int k = idx[q*S + s];
        const float2* kp = (const float2*)(K + (((size_t)b*L + k)*H + h)*D);
        float2 kv = kp[lane];
        float p = qv.x*kv.x + qv.y*kv.y;
        #pragma unroll
        for (int o = 16; o > 0; o >>= 1) p += __shfl_xor_sync(0xffffffffu, p, o);
        mx = fmaxf(mx, p);
        sm += p;
    }
    if (lane == 0) g_M[gw] = mx - sm * (1.0f/(float)L);
}

// ---------------------------------------------------------------------------
// Kernel 2: top-40 per (b,h), descending, ties -> smaller index (lax.top_k)
// one block of 256 per (b,h); iterative argmax with masking
// ---------------------------------------------------------------------------
__global__ void topk_kernel() {
    int bh = blockIdx.x;
    int t  = threadIdx.x;
    __shared__ float vals[L];
    __shared__ float rv[256];
    __shared__ int   ri[256];

    for (int i = t; i < L; i += 256) vals[i] = g_M[bh*L + i];
    __syncthreads();

    for (int u = 0; u < U; u++) {
        float bv = -INFINITY; int bi = L;
        for (int i = t; i < L; i += 256) {
            float v = vals[i];
            if (v > bv || (v == bv && i < bi)) { bv = v; bi = i; }
        }
        rv[t] = bv; ri[t] = bi;
        __syncthreads();
        for (int s = 128; s > 0; s >>= 1) {
            if (t < s) {
                float ov = rv[t+s]; int oi = ri[t+s];
                if (ov > rv[t] || (ov == rv[t] && oi < ri[t])) { rv[t] = ov; ri[t] = oi; }
            }
            __syncthreads();
        }
        if (t == 0) { g_top[bh*U + u] = ri[0]; vals[ri[0]] = -INFINITY; }
        __syncthreads();
    }
}

// ---------------------------------------------------------------------------
// Kernel 3a: per-chunk sums of V over q for each d
// ---------------------------------------------------------------------------
__global__ void chunk_sum_kernel(const float* __restrict__ V) {
    int blk = blockIdx.x;                 // (b*H + h)*NCHUNK + c
    int c   = blk % NCHUNK;
    int bh  = blk / NCHUNK;
    int h   = bh % H, b = bh / H;
    int t   = threadIdx.x;                // 256
    int d   = t & 63, part = t >> 6;      // 4 parts x 32 q's

    const float* vp = V + (((size_t)b*L + c*CHUNK + part*32)*H + h)*D + d;
    float s = 0.f;
    #pragma unroll
    for (int i = 0; i < 32; i++) s += vp[(size_t)i*HD];

    __shared__ float red[4][64];
    red[part][d] = s;
    __syncthreads();
    if (t < 64) g_csum[blk*D + t] = red[0][t] + red[1][t] + red[2][t] + red[3][t];
}

// ---------------------------------------------------------------------------
// Kernel 3b: exclusive prefix over chunks, per (b,h,d)
// ---------------------------------------------------------------------------
__global__ void prefix_kernel() {
    int bh = blockIdx.x;      // 32 blocks
    int t  = threadIdx.x;     // 64
    float run = 0.f;
    #pragma unroll
    for (int c = 0; c < NCHUNK; c++) {
        int o = (bh*NCHUNK + c)*D + t;
        float v = g_csum[o];
        g_csum[o] = run;
        run += v;
    }
}

// ---------------------------------------------------------------------------
// Kernel 3c: in-chunk cumsum + write output (B,L,H,D)
// ---------------------------------------------------------------------------
__global__ void cumsum_kernel(const float* __restrict__ V, float* __restrict__ out) {
    int blk = blockIdx.x;
    int c   = blk % NCHUNK;
    int bh  = blk / NCHUNK;
    int h   = bh % H, b = bh / H;
    int t   = threadIdx.x;    // 256
    __shared__ float tile[CHUNK*D];   // 32KB

    size_t base = (((size_t)b*L + (size_t)c*CHUNK)*H + h)*D;
    for (int e = t; e < CHUNK*D; e += 256) {
        int q = e >> 6, d = e & 63;
        tile[e] = V[base + (size_t)q*HD + d];
    }
    __syncthreads();
    if (t < 64) {
        float acc = g_csum[blk*D + t];
        #pragma unroll
        for (int q = 0; q < CHUNK; q++) {
            acc += tile[q*64 + t];
            tile[q*64 + t] = acc;
        }
    }
    __syncthreads();
    for (int e = t; e < CHUNK*D; e += 256) {
        int q = e >> 6, d = e & 63;
        out[base + (size_t)q*HD + d] = tile[e];
    }
}

// ---------------------------------------------------------------------------
// Kernel 4: attention for the 40 selected queries per (b,h); scatter into out.
// Rank-i row attends only keys 0..i (Informer mask quirk: mask is triu(u,L)).
// ---------------------------------------------------------------------------
__global__ void attn_kernel(const float* __restrict__ Q,
                            const float* __restrict__ K,
                            const float* __restrict__ V,
                            float* __restrict__ out) {
    int bh = blockIdx.x;
    int h  = bh % H, b = bh / H;
    int t  = threadIdx.x;     // 256 = 8 warps
    __shared__ float Ks[U][D], Vs[U][D], Qs[U][D];
    __shared__ int ti[U];

    if (t < U) ti[t] = g_top[bh*U + t];
    __syncthreads();

    for (int e = t; e < U*D; e += 256) {
        int r = e / D, d = e % D;
        Ks[r][d] = K[(((size_t)b*L + r)*H + h)*D + d];
        Vs[r][d] = V[(((size_t)b*L + r)*H + h)*D + d];
        Qs[r][d] = Q[(((size_t)b*L + ti[r])*H + h)*D + d];
    }
    __syncthreads();

    int warp = t >> 5, lane = t & 31;
    for (int i = warp; i < U; i += 8) {
        float2 qv = ((const float2*)Qs[i])[lane];
        float sc[U];
        float mx = -INFINITY;
        for (int k = 0; k <= i; k++) {
            float2 kv = ((const float2*)Ks[k])[lane];
            float p = qv.x*kv.x + qv.y*kv.y;
            #pragma unroll
            for (int o = 16; o > 0; o >>= 1) p += __shfl_xor_sync(0xffffffffu, p, o);
            p *= SCALE;
            sc[k] = p;
            mx = fmaxf(mx, p);
        }
        float denom = 0.f;
        for (int k = 0; k <= i; k++) { sc[k] = expf(sc[k] - mx); denom += sc[k]; }
        float inv = 1.f / denom;
        float2 acc = make_float2(0.f, 0.f);
        for (int k = 0; k <= i; k++) {
            float2 vv = ((const float2*)Vs[k])[lane];
            float w = sc[k] * inv;
            acc.x += w*vv.x;
            acc.y += w*vv.y;
        }
        ((float2*)(out + (((size_t)b*L + ti[i])*H + h)*D))[lane] = acc;
    }
}

// ---------------------------------------------------------------------------
extern "C" void kernel_launch(void* const* d_in, const int* in_sizes, int n_in,
                              void* d_out, int out_size) {
    const float* Q   = (const float*)d_in[0];
    const float* K   = (const float*)d_in[1];
    const float* V   = (const float*)d_in[2];
    const int*   idx = (const int*)d_in[3];
    float* out = (float*)d_out;

    // 1: M scores — one warp per (b,h,q)
    {
        int warps = B*H*L;
        int threads = 256;
        int blocks = (warps*32 + threads - 1) / threads;
        compute_M_kernel<<<blocks, threads>>>(Q, K, idx);
    }
    // 2: top-40 per (b,h)
    topk_kernel<<<B*H, 256>>>();
    // 3: cumsum of V over L
    chunk_sum_kernel<<<B*H*NCHUNK, 256>>>(V);
    prefix_kernel<<<B*H, 64>>>();
    cumsum_kernel<<<B*H*NCHUNK, 256>>>(V, out);
    // 4: sparse attention + scatter (after cumsum writes)
    attn_kernel<<<B*H, 256>>>(Q, K, V, out);
}

// round 4
// speedup vs baseline: 1.2320x; 1.2320x over previous
#include <cuda_runtime.h>
#include <math.h>

#define B 4
#define L 2048
#define H 8
#define D 64
#define S 40
#define U 40
#define HD (H*D)
#define CHUNK 128
#define NCHUNK (L/CHUNK)
#define SCALE 0.125f   /* 1/sqrt(64) */

// scratch (allocation-free rule: __device__ globals)
__device__ float g_M[B*H*L];
__device__ int   g_top[B*H*U];
__device__ float g_csum[B*H*NCHUNK*D];

// ---------------------------------------------------------------------------
// Kernel 1: M[b,h,q] = max_s dot(Q[b,h,q], K[b,h,idx[q,s]]) - sum_s/L
// one warp per (b,h,q); 8 groups of 4 lanes, each group owns one key per batch.
// 5 batches of 8 keys; 4 independent LDG.128 per lane per batch.
// ---------------------------------------------------------------------------
__global__ void compute_M_kernel(const float* __restrict__ Q,
                                 const float* __restrict__ K,
                                 const int*   __restrict__ idx) {
    int gw   = (blockIdx.x * blockDim.x + threadIdx.x) >> 5;
    int lane = threadIdx.x & 31;
    if (gw >= B*H*L) return;
    int q = gw % L;
    int h = (gw / L) % H;
    int b = gw / (L*H);
    int sub = lane & 3;      // 16-float slice of D within the group
    int g   = lane >> 2;     // which key in the batch (0..7)

    const float4* qp = (const float4*)(Q + (((size_t)b*L + q)*H + h)*D) + sub*4;
    float4 q0 = qp[0], q1 = qp[1], q2 = qp[2], q3 = qp[3];

    const int* ip = idx + q*S;
    const size_t bhK = ((size_t)b*L)*HD + (size_t)h*D;

    float mx = -INFINITY, sm = 0.f;
    #pragma unroll
    for (int sb = 0; sb < 5; sb++) {
        int k = __ldg(ip + sb*8 + g);
        const float4* kp = (const float4*)(K + bhK + (size_t)k*HD) + sub*4;
        float4 k0 = kp[0], k1 = kp[1], k2 = kp[2], k3 = kp[3];
        float p = q0.x*k0.x + q0.y*k0.y + q0.z*k0.z + q0.w*k0.w
                + q1.x*k1.x + q1.y*k1.y + q1.z*k1.z + q1.w*k1.w
                + q2.x*k2.x + q2.y*k2.y + q2.z*k2.z + q2.w*k2.w
                + q3.x*k3.x + q3.y*k3.y + q3.z*k3.z + q3.w*k3.w;
        // reduce within 4-lane group -> every lane of group holds the full dot
        p += __shfl_xor_sync(0xffffffffu, p, 1);
        p += __shfl_xor_sync(0xffffffffu, p, 2);
        mx = fmaxf(mx, p);
        sm += p;
    }
    // reduce across the 8 groups (values uniform within each group)
    #pragma unroll
    for (int o = 4; o <= 16; o <<= 1) {
        mx = fmaxf(mx, __shfl_xor_sync(0xffffffffu, mx, o));
        sm += __shfl_xor_sync(0xffffffffu, sm, o);
    }
    if (lane == 0) g_M[gw] = mx - sm * (1.0f/(float)L);
}

// ---------------------------------------------------------------------------
// Kernel 2: top-40 per (b,h), descending, ties -> smaller index (lax.top_k)
// one WARP per (b,h); values register-resident as order-preserving uint32.
// Packed (val, ~idx) u64 butterfly max; loser lane rescans its 64 slots.
// ---------------------------------------------------------------------------
__device__ __forceinline__ unsigned order_f32(float v) {
    unsigned u = __float_as_uint(v);
    return (u & 0x80000000u) ? ~u : (u | 0x80000000u);
}

__global__ void topk_kernel() {
    int bh   = blockIdx.x;
    int lane = threadIdx.x;           // block = 32
    const float* M = g_M + bh*L;

    unsigned ov[64];
    #pragma unroll
    for (int j = 0; j < 64; j++) ov[j] = order_f32(M[j*32 + lane]);

    unsigned long long removed = 0ull;

    // initial local best (ascending j => smallest element index wins ties via >)
    unsigned bv = 0; int bslot = 0;
    #pragma unroll
    for (int j = 0; j < 64; j++) if (ov[j] > bv) { bv = ov[j]; bslot = j; }

    for (int u = 0; u < U; u++) {
        unsigned long long key =
            ((unsigned long long)bv << 32) | (unsigned)(~(unsigned)(bslot*32 + lane));
        #pragma unroll
        for (int o = 16; o > 0; o >>= 1) {
            unsigned long long ok = __shfl_xor_sync(0xffffffffu, key, o);
            if (ok > key) key = ok;
        }
        int widx = (int)(~(unsigned)key);       // winning element index
        if (lane == 0) g_top[bh*U + u] = widx;
        if ((widx & 31) == lane) {
            removed |= 1ull << (widx >> 5);
            bv = 0; bslot = 0;
            #pragma unroll
            for (int j = 0; j < 64; j++) {
                unsigned v = ((removed >> j) & 1ull) ? 0u : ov[j];
                if (v > bv) { bv = v; bslot = j; }
            }
        }
    }
}

// ---------------------------------------------------------------------------
// Kernel 3a: per-chunk sums of V over q for each d
// ---------------------------------------------------------------------------
__global__ void chunk_sum_kernel(const float* __restrict__ V) {
    int blk = blockIdx.x;                 // (b*H + h)*NCHUNK + c
    int c   = blk % NCHUNK;
    int bh  = blk / NCHUNK;
    int h   = bh % H, b = bh / H;
    int t   = threadIdx.x;                // 256
    int d   = t & 63, part = t >> 6;      // 4 parts x 32 q's

    const float* vp = V + (((size_t)b*L + c*CHUNK + part*32)*H + h)*D + d;
    float s = 0.f;
    #pragma unroll
    for (int i = 0; i < 32; i++) s += vp[(size_t)i*HD];

    __shared__ float red[4][64];
    red[part][d] = s;
    __syncthreads();
    if (t < 64) g_csum[blk*D + t] = red[0][t] + red[1][t] + red[2][t] + red[3][t];
}

// ---------------------------------------------------------------------------
// Kernel 3b: in-chunk cumsum + inlined cross-chunk prefix + write out (B,L,H,D)
// ---------------------------------------------------------------------------
__global__ void cumsum_kernel(const float* __restrict__ V, float* __restrict__ out) {
    int blk = blockIdx.x;
    int c   = blk % NCHUNK;
    int bh  = blk / NCHUNK;
    int h   = bh % H, b = bh / H;
    int t   = threadIdx.x;    // 256
    __shared__ float tile[CHUNK*D];   // 32KB
    __shared__ float offs[D];

    // exclusive prefix over preceding chunks (independent loads, MLP up to 15)
    if (t < 64) {
        float o = 0.f;
        for (int cc = 0; cc < c; cc++) o += g_csum[(bh*NCHUNK + cc)*D + t];
        offs[t] = o;
    }

    size_t base = (((size_t)b*L + (size_t)c*CHUNK)*H + h)*D;
    for (int e = t; e < CHUNK*D; e += 256) {
        int q = e >> 6, d = e & 63;
        tile[e] = V[base + (size_t)q*HD + d];
    }
    __syncthreads();
    if (t < 64) {
        float acc = offs[t];
        #pragma unroll
        for (int q = 0; q < CHUNK; q++) {
            acc += tile[q*64 + t];
            tile[q*64 + t] = acc;
        }
    }
    __syncthreads();
    for (int e = t; e < CHUNK*D; e += 256) {
        int q = e >> 6, d = e & 63;
        out[base + (size_t)q*HD + d] = tile[e];
    }
}

// ---------------------------------------------------------------------------
// Kernel 4: attention for the 40 selected queries per (b,h); scatter into out.
// Rank-i row attends only keys 0..i (Informer mask quirk: mask is triu(u,L)).
// ---------------------------------------------------------------------------
__global__ void attn_kernel(const float* __restrict__ Q,
                            const float* __restrict__ K,
                            const float* __restrict__ V,
                            float* __restrict__ out) {
    int bh = blockIdx.x;
    int h  = bh % H, b = bh / H;
    int t  = threadIdx.x;     // 256 = 8 warps
    __shared__ float Ks[U][D], Vs[U][D], Qs[U][D];
    __shared__ int ti[U];

    if (t < U) ti[t] = g_top[bh*U + t];
    __syncthreads();

    for (int e = t; e < U*D; e += 256) {
        int r = e / D, d = e % D;
        Ks[r][d] = K[(((size_t)b*L + r)*H + h)*D + d];
        Vs[r][d] = V[(((size_t)b*L + r)*H + h)*D + d];
        Qs[r][d] = Q[(((size_t)b*L + ti[r])*H + h)*D + d];
    }
    __syncthreads();

    int warp = t >> 5, lane = t & 31;
    for (int i = warp; i < U; i += 8) {
        float2 qv = ((const float2*)Qs[i])[lane];
        float sc[U];
        float mx = -INFINITY;
        for (int k = 0; k <= i; k++) {
            float2 kv = ((const float2*)Ks[k])[lane];
            float p = qv.x*kv.x + qv.y*kv.y;
            #pragma unroll
            for (int o = 16; o > 0; o >>= 1) p += __shfl_xor_sync(0xffffffffu, p, o);
            p *= SCALE;
            sc[k] = p;
            mx = fmaxf(mx, p);
        }
        float denom = 0.f;
        for (int k = 0; k <= i; k++) { sc[k] = expf(sc[k] - mx); denom += sc[k]; }
        float inv = 1.f / denom;
        float2 acc = make_float2(0.f, 0.f);
        for (int k = 0; k <= i; k++) {
            float2 vv = ((const float2*)Vs[k])[lane];
            float w = sc[k] * inv;
            acc.x += w*vv.x;
            acc.y += w*vv.y;
        }
        ((float2*)(out + (((size_t)b*L + ti[i])*H + h)*D))[lane] = acc;
    }
}

// ---------------------------------------------------------------------------
extern "C" void kernel_launch(void* const* d_in, const int* in_sizes, int n_in,
                              void* d_out, int out_size) {
    const float* Q   = (const float*)d_in[0];
    const float* K   = (const float*)d_in[1];
    const float* V   = (const float*)d_in[2];
    const int*   idx = (const int*)d_in[3];
    float* out = (float*)d_out;

    // 1: M scores — one warp per (b,h,q)
    {
        int warps = B*H*L;
        int threads = 256;
        int blocks = (warps*32 + threads - 1) / threads;
        compute_M_kernel<<<blocks, threads>>>(Q, K, idx);
    }
    // 2: top-40 per (b,h) — one warp per (b,h)
    topk_kernel<<<B*H, 32>>>();
    // 3: cumsum of V over L (chunk sums, then in-chunk scan w/ inlined prefix)
    chunk_sum_kernel<<<B*H*NCHUNK, 256>>>(V);
    cumsum_kernel<<<B*H*NCHUNK, 256>>>(V, out);
    // 4: sparse attention + scatter (after cumsum writes)
    attn_kernel<<<B*H, 256>>>(Q, K, V, out);
}